// round 3
// baseline (speedup 1.0000x reference)
#include <cuda_runtime.h>
#include <cstdint>

#define NN    50000
#define NE    600000
#define TE    (NE + NN)
#define HD    128
#define BB    128
#define KSEL  30
#define COUT  32
#define KERW  5
#define LOUT  26
#define ODIM  10
#define PSTR  129
#define DSLOT 64      // fixed per-node edge slots (Poisson(13) -> max deg << 64)

// ---------------- device scratch ----------------
static __device__ int   g_cur[NN];
static __device__ float g_dinv[NN];
static __device__ int   g_srcv[NN * DSLOT];
static __device__ float g_hw[NN * HD];
static __device__ float g_hA[NN * HD];
static __device__ float g_hB[NN * HD];

// ---------------- f32x2 packed helpers ----------------
__device__ __forceinline__ unsigned long long pk2(float a, float b) {
    unsigned long long r;
    asm("mov.b64 %0, {%1, %2};" : "=l"(r) : "f"(a), "f"(b));
    return r;
}
__device__ __forceinline__ void fma2(unsigned long long& d, unsigned long long a, unsigned long long b) {
    asm("fma.rn.f32x2 %0, %1, %2, %0;" : "+l"(d) : "l"(a), "l"(b));
}

// ---------------- graph build (bucketed, no scan) ----------------
__global__ void k_init() {
    int i = blockIdx.x * 256 + threadIdx.x;
    if (i < NN) g_cur[i] = 0;
}

__global__ void k_fill(const int* __restrict__ ei) {
    int e = blockIdx.x * 256 + threadIdx.x;
    if (e >= TE) return;
    int src, dst;
    if (e < NE) { src = ei[e]; dst = ei[NE + e]; }
    else        { src = dst = e - NE; }          // self-loop
    int pos = atomicAdd(&g_cur[dst], 1);
    if (pos < DSLOT) g_srcv[dst * DSLOT + pos] = src;
}

__global__ void k_dinv() {
    int i = blockIdx.x * 256 + threadIdx.x;
    if (i < NN) g_dinv[i] = rsqrtf((float)g_cur[i]);
}

// ---------------- GEMM: g_hw = A(NNxHD) @ W(HDxHD) ----------------
// 128 threads, block tile 128x128, two N-passes of 64 cols.
// Thread tile: 8 rows x 8 cols (cols = n0 + tx*4 and n0 + 32 + tx*4).
// 64 acc regs -> >=3 blocks/SM -> grid 391 fits in ONE wave.
__global__ __launch_bounds__(128, 3) void k_gemm(const float* __restrict__ A,
                                                 const float* __restrict__ W) {
    __shared__ float Ash[32][132];   // [k][m] transposed, padded
    __shared__ float Bsh[32][68];    // [k][n-half], padded
    const int tid = threadIdx.x;
    const int m0 = blockIdx.x * 128;
    const int ty = tid >> 3;         // 0..15 -> rows ty*8..+8
    const int tx = tid & 7;          // 0..7

    #pragma unroll
    for (int pass = 0; pass < 2; pass++) {
        const int n0 = pass * 64;
        unsigned long long acc[8][4];
        #pragma unroll
        for (int i = 0; i < 8; i++)
            #pragma unroll
            for (int j = 0; j < 4; j++) acc[i][j] = 0ULL;

        for (int k0 = 0; k0 < HD; k0 += 32) {
            // A tile: 128 rows x 32 k = 1024 float4, 8 per thread, transpose into Ash
            #pragma unroll
            for (int s = 0; s < 8; s++) {
                int idx = s * 128 + tid;
                int m = idx >> 3, q = idx & 7;
                int row = m0 + m;
                float4 v = make_float4(0.f, 0.f, 0.f, 0.f);
                if (row < NN) v = *reinterpret_cast<const float4*>(&A[row * HD + k0 + q * 4]);
                Ash[q * 4 + 0][m] = v.x; Ash[q * 4 + 1][m] = v.y;
                Ash[q * 4 + 2][m] = v.z; Ash[q * 4 + 3][m] = v.w;
            }
            // B tile: 32 k x 64 n = 512 float4, 4 per thread
            #pragma unroll
            for (int s = 0; s < 4; s++) {
                int idx = s * 128 + tid;
                int k = idx >> 4, n4 = (idx & 15) * 4;
                *reinterpret_cast<float4*>(&Bsh[k][n4]) =
                    *reinterpret_cast<const float4*>(&W[(k0 + k) * HD + n0 + n4]);
            }
            __syncthreads();
            #pragma unroll 8
            for (int k = 0; k < 32; k++) {
                float4 a0 = *reinterpret_cast<const float4*>(&Ash[k][ty * 8]);
                float4 a1 = *reinterpret_cast<const float4*>(&Ash[k][ty * 8 + 4]);
                float av[8] = {a0.x, a0.y, a0.z, a0.w, a1.x, a1.y, a1.z, a1.w};
                ulonglong2 b0 = *reinterpret_cast<const ulonglong2*>(&Bsh[k][tx * 4]);
                ulonglong2 b1 = *reinterpret_cast<const ulonglong2*>(&Bsh[k][32 + tx * 4]);
                unsigned long long bv[4] = {b0.x, b0.y, b1.x, b1.y};
                #pragma unroll
                for (int i = 0; i < 8; i++) {
                    unsigned long long ad = pk2(av[i], av[i]);
                    #pragma unroll
                    for (int j = 0; j < 4; j++) fma2(acc[i][j], ad, bv[j]);
                }
            }
            __syncthreads();
        }
        // epilogue: two float4 stores per row
        #pragma unroll
        for (int i = 0; i < 8; i++) {
            int row = m0 + ty * 8 + i;
            if (row < NN) {
                union { unsigned long long u[2]; float4 f; } p0, p1;
                p0.u[0] = acc[i][0]; p0.u[1] = acc[i][1];
                p1.u[0] = acc[i][2]; p1.u[1] = acc[i][3];
                *reinterpret_cast<float4*>(&g_hw[row * HD + n0 + tx * 4])      = p0.f;
                *reinterpret_cast<float4*>(&g_hw[row * HD + n0 + 32 + tx * 4]) = p1.f;
            }
        }
    }
}

// ---------------- aggregation: warp per node, index+dinv prefetch ----------------
__global__ __launch_bounds__(256) void k_agg(const float* __restrict__ bias,
                                             float* __restrict__ hout) {
    int w = (blockIdx.x * 256 + threadIdx.x) >> 5;
    int lane = threadIdx.x & 31;
    if (w >= NN) return;
    int deg = g_cur[w]; if (deg > DSLOT) deg = DSLOT;
    const int* lst = &g_srcv[w * DSLOT];

    // prefetch indices + dinv for all neighbors into registers (warp-distributed)
    int idxA = (lane < deg)      ? __ldg(&lst[lane])      : 0;
    int idxB = (32 + lane < deg) ? __ldg(&lst[32 + lane]) : 0;
    float dA = __ldg(&g_dinv[idxA]);
    float dB = __ldg(&g_dinv[idxB]);

    const float4* hw4 = reinterpret_cast<const float4*>(g_hw);
    float4 acc = make_float4(0.f, 0.f, 0.f, 0.f);

    int e = 0;
    for (; e + 4 <= deg; e += 4) {
        int   s0, s1, s2, s3;
        float c0, c1, c2, c3;
        {
            int  ia = (e + 0 < 32) ? idxA : idxB;  float fa = (e + 0 < 32) ? dA : dB;
            s0 = __shfl_sync(0xFFFFFFFFu, ia, (e + 0) & 31);
            c0 = __shfl_sync(0xFFFFFFFFu, fa, (e + 0) & 31);
            int  ib = (e + 1 < 32) ? idxA : idxB;  float fb = (e + 1 < 32) ? dA : dB;
            s1 = __shfl_sync(0xFFFFFFFFu, ib, (e + 1) & 31);
            c1 = __shfl_sync(0xFFFFFFFFu, fb, (e + 1) & 31);
            int  ic = (e + 2 < 32) ? idxA : idxB;  float fc = (e + 2 < 32) ? dA : dB;
            s2 = __shfl_sync(0xFFFFFFFFu, ic, (e + 2) & 31);
            c2 = __shfl_sync(0xFFFFFFFFu, fc, (e + 2) & 31);
            int  id = (e + 3 < 32) ? idxA : idxB;  float fd = (e + 3 < 32) ? dA : dB;
            s3 = __shfl_sync(0xFFFFFFFFu, id, (e + 3) & 31);
            c3 = __shfl_sync(0xFFFFFFFFu, fd, (e + 3) & 31);
        }
        float4 v0 = __ldg(&hw4[s0 * 32 + lane]);
        float4 v1 = __ldg(&hw4[s1 * 32 + lane]);
        float4 v2 = __ldg(&hw4[s2 * 32 + lane]);
        float4 v3 = __ldg(&hw4[s3 * 32 + lane]);
        acc.x += c0 * v0.x + c1 * v1.x + c2 * v2.x + c3 * v3.x;
        acc.y += c0 * v0.y + c1 * v1.y + c2 * v2.y + c3 * v3.y;
        acc.z += c0 * v0.z + c1 * v1.z + c2 * v2.z + c3 * v3.z;
        acc.w += c0 * v0.w + c1 * v1.w + c2 * v2.w + c3 * v3.w;
    }
    for (; e < deg; e++) {
        int   ia = (e < 32) ? idxA : idxB;
        float fa = (e < 32) ? dA : dB;
        int   s = __shfl_sync(0xFFFFFFFFu, ia, e & 31);
        float c = __shfl_sync(0xFFFFFFFFu, fa, e & 31);
        float4 v = __ldg(&hw4[s * 32 + lane]);
        acc.x += c * v.x; acc.y += c * v.y; acc.z += c * v.z; acc.w += c * v.w;
    }

    float dn = g_dinv[w];
    float4 bb = reinterpret_cast<const float4*>(bias)[lane];
    float4 r;
    r.x = fmaxf(acc.x * dn + bb.x, 0.f);
    r.y = fmaxf(acc.y * dn + bb.y, 0.f);
    r.z = fmaxf(acc.z * dn + bb.z, 0.f);
    r.w = fmaxf(acc.w * dn + bb.w, 0.f);
    reinterpret_cast<float4*>(hout)[w * 32 + lane] = r;
}

// ---------------- sort-pool + conv1d + MLP ----------------
__device__ __forceinline__ int lbound(const int* __restrict__ a, int n, int key) {
    int lo = 0, hi = n;
    while (lo < hi) { int mid = (lo + hi) >> 1; if (a[mid] < key) lo = mid + 1; else hi = mid; }
    return lo;
}

__global__ __launch_bounds__(256) void k_head(const int* __restrict__ batch,
                                              const float* __restrict__ h,
                                              const float* __restrict__ cw,
                                              const float* __restrict__ cb,
                                              const float* __restrict__ l1w,
                                              const float* __restrict__ l1b,
                                              const float* __restrict__ l2w,
                                              const float* __restrict__ l2b,
                                              float* __restrict__ out) {
    const int b = blockIdx.x, tid = threadIdx.x;
    const int lane = tid & 31, wid = tid >> 5;
    const int start = lbound(batch, NN, b);
    const int end   = lbound(batch, NN, b + 1);
    int cnt = end - start;
    if (cnt > 1024) cnt = 1024;

    __shared__ unsigned long long skeys[1024];
    __shared__ unsigned long long wred[8];
    __shared__ int sel[KSEL];
    __shared__ float pooled[KSEL * PSTR];
    __shared__ float flat[COUT * LOUT];
    __shared__ float zz[HD];

    for (int i = tid; i < cnt; i += 256) {
        float v = h[(start + i) * HD + (HD - 1)];
        unsigned u = __float_as_uint(v);
        if (v == 0.0f) u = 0u;
        skeys[i] = ((unsigned long long)u << 32) |
                   (unsigned long long)(0xFFFFFFFFu - (unsigned)i);
    }
    for (int i = tid; i < KSEL * PSTR; i += 256) pooled[i] = 0.f;
    __syncthreads();

    const int m = (cnt < KSEL) ? cnt : KSEL;
    for (int r = 0; r < m; r++) {
        unsigned long long best = 0ULL;
        for (int i = tid; i < cnt; i += 256) {
            unsigned long long k = skeys[i];
            if (k > best) best = k;
        }
        #pragma unroll
        for (int off = 16; off > 0; off >>= 1) {
            unsigned long long o = __shfl_xor_sync(0xFFFFFFFFu, best, off);
            if (o > best) best = o;
        }
        if (lane == 0) wred[wid] = best;
        __syncthreads();
        if (tid == 0) {
            unsigned long long bk = 0ULL;
            #pragma unroll
            for (int q = 0; q < 8; q++) if (wred[q] > bk) bk = wred[q];
            int i = (int)(0xFFFFFFFFu - (unsigned)(bk & 0xFFFFFFFFull));
            sel[r] = start + i;
            skeys[i] = 0ULL;
        }
        __syncthreads();
    }

    for (int idx = tid; idx < m * HD; idx += 256) {
        int r = idx >> 7, c = idx & 127;
        pooled[r * PSTR + c] = h[sel[r] * HD + c];
    }
    __syncthreads();

    for (int ot = tid; ot < COUT * LOUT; ot += 256) {
        int o = ot / LOUT, t = ot % LOUT;
        float s = __ldg(&cb[o]);
        const float* wo = cw + o * HD * KERW;
        for (int c = 0; c < HD; c++) {
            float w0 = __ldg(&wo[c * KERW + 0]);
            float w1 = __ldg(&wo[c * KERW + 1]);
            float w2 = __ldg(&wo[c * KERW + 2]);
            float w3 = __ldg(&wo[c * KERW + 3]);
            float w4 = __ldg(&wo[c * KERW + 4]);
            s += pooled[(t + 0) * PSTR + c] * w0;
            s += pooled[(t + 1) * PSTR + c] * w1;
            s += pooled[(t + 2) * PSTR + c] * w2;
            s += pooled[(t + 3) * PSTR + c] * w3;
            s += pooled[(t + 4) * PSTR + c] * w4;
        }
        flat[ot] = fmaxf(s, 0.f);
    }
    __syncthreads();

    if (tid < HD) {
        float s = __ldg(&l1b[tid]);
        #pragma unroll 8
        for (int i = 0; i < COUT * LOUT; i++)
            s += flat[i] * __ldg(&l1w[i * HD + tid]);
        zz[tid] = fmaxf(s, 0.f);
    }
    __syncthreads();

    if (tid < ODIM) {
        float s = __ldg(&l2b[tid]);
        #pragma unroll 8
        for (int i = 0; i < HD; i++)
            s += zz[i] * __ldg(&l2w[i * ODIM + tid]);
        out[b * ODIM + tid] = s;
    }
}

// ---------------- launch ----------------
static cudaStream_t g_s2 = nullptr;
static cudaEvent_t  g_e0 = nullptr, g_e1 = nullptr;

extern "C" void kernel_launch(void* const* d_in, const int* in_sizes, int n_in,
                              void* d_out, int out_size) {
    const float* x     = (const float*)d_in[0];
    const int*   ei    = (const int*)  d_in[1];
    const int*   batch = (const int*)  d_in[2];
    const float* W0 = (const float*)d_in[3];  const float* b0 = (const float*)d_in[4];
    const float* W1 = (const float*)d_in[5];  const float* b1 = (const float*)d_in[6];
    const float* W2 = (const float*)d_in[7];  const float* b2 = (const float*)d_in[8];
    const float* cw = (const float*)d_in[9];  const float* cb = (const float*)d_in[10];
    const float* l1w = (const float*)d_in[11]; const float* l1b = (const float*)d_in[12];
    const float* l2w = (const float*)d_in[13]; const float* l2b = (const float*)d_in[14];
    float* out = (float*)d_out;

    if (g_s2 == nullptr) {
        cudaStreamCreateWithFlags(&g_s2, cudaStreamNonBlocking);
        cudaEventCreateWithFlags(&g_e0, cudaEventDisableTiming);
        cudaEventCreateWithFlags(&g_e1, cudaEventDisableTiming);
    }
    const bool fork = (g_s2 != nullptr && g_e0 != nullptr && g_e1 != nullptr);
    cudaStream_t cs = fork ? g_s2 : (cudaStream_t)0;

    void *pA = nullptr, *pB = nullptr;
    cudaGetSymbolAddress(&pA, g_hA);
    cudaGetSymbolAddress(&pB, g_hB);
    float* hA = (float*)pA;
    float* hB = (float*)pB;

    if (fork) {
        cudaEventRecord(g_e0, 0);
        cudaStreamWaitEvent(cs, g_e0, 0);
    }
    k_init<<<(NN + 255) / 256, 256, 0, cs>>>();
    k_fill<<<(TE + 255) / 256, 256, 0, cs>>>(ei);
    k_dinv<<<(NN + 255) / 256, 256, 0, cs>>>();
    if (fork) cudaEventRecord(g_e1, cs);

    const int gemm_blocks = (NN + 127) / 128;   // 391
    const int agg_blocks  = (NN + 7) / 8;

    k_gemm<<<gemm_blocks, 128>>>(x, W0);
    if (fork) cudaStreamWaitEvent(0, g_e1, 0);
    k_agg <<<agg_blocks, 256>>>(b0, hA);

    k_gemm<<<gemm_blocks, 128>>>(hA, W1);
    k_agg <<<agg_blocks, 256>>>(b1, hB);

    k_gemm<<<gemm_blocks, 128>>>(hB, W2);
    k_agg <<<agg_blocks, 256>>>(b2, hA);

    k_head<<<BB, 256>>>(batch, hA, cw, cb, l1w, l1b, l2w, l2b, out);
}

// round 4
// speedup vs baseline: 1.0287x; 1.0287x over previous
#include <cuda_runtime.h>
#include <cstdint>

#define NN    50000
#define NE    600000
#define TE    (NE + NN)
#define HD    128
#define BB    128
#define KSEL  30
#define COUT  32
#define KERW  5
#define LOUT  26
#define ODIM  10
#define PSTR  129
#define DSLOT 64      // fixed per-node edge slots (Poisson(13) -> max deg << 64)

// ---------------- device scratch ----------------
static __device__ int   g_cur[NN];
static __device__ float g_dinv[NN];
static __device__ __align__(16) int g_srcv[NN * DSLOT];
static __device__ float g_hw[NN * HD];
static __device__ float g_hA[NN * HD];
static __device__ float g_hB[NN * HD];

// ---------------- f32x2 packed helpers ----------------
__device__ __forceinline__ unsigned long long pk2(float a, float b) {
    unsigned long long r;
    asm("mov.b64 %0, {%1, %2};" : "=l"(r) : "f"(a), "f"(b));
    return r;
}
__device__ __forceinline__ void fma2(unsigned long long& d, unsigned long long a, unsigned long long b) {
    asm("fma.rn.f32x2 %0, %1, %2, %0;" : "+l"(d) : "l"(a), "l"(b));
}

// ---------------- graph build (bucketed, no scan) ----------------
__global__ void k_init() {
    int i = blockIdx.x * 256 + threadIdx.x;
    if (i < NN) g_cur[i] = 0;
}

__global__ void k_fill(const int* __restrict__ ei) {
    int e = blockIdx.x * 256 + threadIdx.x;
    if (e >= TE) return;
    int src, dst;
    if (e < NE) { src = ei[e]; dst = ei[NE + e]; }
    else        { src = dst = e - NE; }          // self-loop
    int pos = atomicAdd(&g_cur[dst], 1);
    if (pos < DSLOT) g_srcv[dst * DSLOT + pos] = src;
}

__global__ void k_dinv() {
    int i = blockIdx.x * 256 + threadIdx.x;
    if (i < NN) g_dinv[i] = rsqrtf((float)g_cur[i]);
}

// ---------------- GEMM: g_hw = A(NNxHD) @ W(HDxHD) ----------------
// 256 threads, block tile 128x128, thread tile 8 rows x 8 cols.
// Cols: tx*4..+3 and 64+tx*4..+3 (tx=0..15) -> 2-phase minimum LDS, no conflicts.
// ~110 regs -> 2 blocks/SM -> 16 warps/SM.
__global__ __launch_bounds__(256, 2) void k_gemm(const float* __restrict__ A,
                                                 const float* __restrict__ W) {
    __shared__ float Ash[16][132];   // [k][m] transposed, padded
    __shared__ float Bsh[16][128];   // [k][n]
    const int tid = threadIdx.x;
    const int m0 = blockIdx.x * 128;
    const int ty = tid >> 4;         // 0..15 -> rows ty*8..+8
    const int tx = tid & 15;         // 0..15 -> cols {tx*4, 64+tx*4}

    unsigned long long acc[8][4];
    #pragma unroll
    for (int i = 0; i < 8; i++)
        #pragma unroll
        for (int j = 0; j < 4; j++) acc[i][j] = 0ULL;

    for (int k0 = 0; k0 < HD; k0 += 16) {
        // A tile: 128 rows x 16 k = 512 float4, 2 per thread, transposed store
        #pragma unroll
        for (int s = 0; s < 2; s++) {
            int idx = s * 256 + tid;
            int m = idx >> 2, q = idx & 3;
            int row = m0 + m;
            float4 v = make_float4(0.f, 0.f, 0.f, 0.f);
            if (row < NN) v = *reinterpret_cast<const float4*>(&A[row * HD + k0 + q * 4]);
            Ash[q * 4 + 0][m] = v.x; Ash[q * 4 + 1][m] = v.y;
            Ash[q * 4 + 2][m] = v.z; Ash[q * 4 + 3][m] = v.w;
        }
        // B tile: 16 k x 128 n = 512 float4, 2 per thread
        #pragma unroll
        for (int s = 0; s < 2; s++) {
            int idx = s * 256 + tid;
            int k = idx >> 5, n4 = (idx & 31) * 4;
            *reinterpret_cast<float4*>(&Bsh[k][n4]) =
                *reinterpret_cast<const float4*>(&W[(k0 + k) * HD + n4]);
        }
        __syncthreads();
        #pragma unroll
        for (int k = 0; k < 16; k++) {
            float4 a0 = *reinterpret_cast<const float4*>(&Ash[k][ty * 8]);
            float4 a1 = *reinterpret_cast<const float4*>(&Ash[k][ty * 8 + 4]);
            float av[8] = {a0.x, a0.y, a0.z, a0.w, a1.x, a1.y, a1.z, a1.w};
            ulonglong2 b0 = *reinterpret_cast<const ulonglong2*>(&Bsh[k][tx * 4]);
            ulonglong2 b1 = *reinterpret_cast<const ulonglong2*>(&Bsh[k][64 + tx * 4]);
            unsigned long long bv[4] = {b0.x, b0.y, b1.x, b1.y};
            #pragma unroll
            for (int i = 0; i < 8; i++) {
                unsigned long long ad = pk2(av[i], av[i]);
                #pragma unroll
                for (int j = 0; j < 4; j++) fma2(acc[i][j], ad, bv[j]);
            }
        }
        __syncthreads();
    }
    #pragma unroll
    for (int i = 0; i < 8; i++) {
        int row = m0 + ty * 8 + i;
        if (row < NN) {
            union { unsigned long long u[2]; float4 f; } p0, p1;
            p0.u[0] = acc[i][0]; p0.u[1] = acc[i][1];
            p1.u[0] = acc[i][2]; p1.u[1] = acc[i][3];
            *reinterpret_cast<float4*>(&g_hw[row * HD + tx * 4])      = p0.f;
            *reinterpret_cast<float4*>(&g_hw[row * HD + 64 + tx * 4]) = p1.f;
        }
    }
}

// ---------------- aggregation: warp per node ----------------
// GATHER_DINV: input rows need per-src dinv scaling (layer 1 only).
// SCALE_OUT:   multiply relu output by dinv[w] before store (feeds next GEMM).
template<bool GATHER_DINV, bool SCALE_OUT>
__global__ __launch_bounds__(256) void k_agg(const float* __restrict__ bias,
                                             float* __restrict__ hout) {
    int w = (blockIdx.x * 256 + threadIdx.x) >> 5;
    int lane = threadIdx.x & 31;
    if (w >= NN) return;
    int deg = g_cur[w]; if (deg > DSLOT) deg = DSLOT;
    const int4* lst4 = reinterpret_cast<const int4*>(&g_srcv[w * DSLOT]);
    const float4* hw4 = reinterpret_cast<const float4*>(g_hw);
    float4 acc = make_float4(0.f, 0.f, 0.f, 0.f);

    int nq = (deg + 3) >> 2;               // number of index quads
    int4 q = __ldg(&lst4[0]);              // prefetch first quad
    for (int iq = 0; iq < nq; iq++) {
        int4 qn;
        if (iq + 1 < nq) qn = __ldg(&lst4[iq + 1]);   // prefetch next
        int base = iq * 4;
        int rem = deg - base;              // >=1
        int s0 = q.x, s1 = q.y, s2 = q.z, s3 = q.w;
        if (rem >= 4) {
            float c0 = 1.f, c1 = 1.f, c2 = 1.f, c3 = 1.f;
            if (GATHER_DINV) {
                c0 = __ldg(&g_dinv[s0]); c1 = __ldg(&g_dinv[s1]);
                c2 = __ldg(&g_dinv[s2]); c3 = __ldg(&g_dinv[s3]);
            }
            float4 v0 = __ldg(&hw4[s0 * 32 + lane]);
            float4 v1 = __ldg(&hw4[s1 * 32 + lane]);
            float4 v2 = __ldg(&hw4[s2 * 32 + lane]);
            float4 v3 = __ldg(&hw4[s3 * 32 + lane]);
            if (GATHER_DINV) {
                acc.x += c0 * v0.x + c1 * v1.x + c2 * v2.x + c3 * v3.x;
                acc.y += c0 * v0.y + c1 * v1.y + c2 * v2.y + c3 * v3.y;
                acc.z += c0 * v0.z + c1 * v1.z + c2 * v2.z + c3 * v3.z;
                acc.w += c0 * v0.w + c1 * v1.w + c2 * v2.w + c3 * v3.w;
            } else {
                acc.x += v0.x + v1.x + v2.x + v3.x;
                acc.y += v0.y + v1.y + v2.y + v3.y;
                acc.z += v0.z + v1.z + v2.z + v3.z;
                acc.w += v0.w + v1.w + v2.w + v3.w;
            }
        } else {
            int ss[3] = {s0, s1, s2};
            for (int u = 0; u < rem; u++) {
                int s = ss[u];
                float c = GATHER_DINV ? __ldg(&g_dinv[s]) : 1.f;
                float4 v = __ldg(&hw4[s * 32 + lane]);
                acc.x += c * v.x; acc.y += c * v.y;
                acc.z += c * v.z; acc.w += c * v.w;
            }
        }
        q = qn;
    }

    float dn = g_dinv[w];
    float4 bb = reinterpret_cast<const float4*>(bias)[lane];
    float4 r;
    r.x = fmaxf(acc.x * dn + bb.x, 0.f);
    r.y = fmaxf(acc.y * dn + bb.y, 0.f);
    r.z = fmaxf(acc.z * dn + bb.z, 0.f);
    r.w = fmaxf(acc.w * dn + bb.w, 0.f);
    if (SCALE_OUT) { r.x *= dn; r.y *= dn; r.z *= dn; r.w *= dn; }
    reinterpret_cast<float4*>(hout)[w * 32 + lane] = r;
}

// ---------------- sort-pool + conv1d + MLP ----------------
__device__ __forceinline__ int lbound(const int* __restrict__ a, int n, int key) {
    int lo = 0, hi = n;
    while (lo < hi) { int mid = (lo + hi) >> 1; if (a[mid] < key) lo = mid + 1; else hi = mid; }
    return lo;
}

__global__ __launch_bounds__(256) void k_head(const int* __restrict__ batch,
                                              const float* __restrict__ h,
                                              const float* __restrict__ cw,
                                              const float* __restrict__ cb,
                                              const float* __restrict__ l1w,
                                              const float* __restrict__ l1b,
                                              const float* __restrict__ l2w,
                                              const float* __restrict__ l2b,
                                              float* __restrict__ out) {
    const int b = blockIdx.x, tid = threadIdx.x;
    const int lane = tid & 31, wid = tid >> 5;
    const int start = lbound(batch, NN, b);
    const int end   = lbound(batch, NN, b + 1);
    int cnt = end - start;
    if (cnt > 1024) cnt = 1024;

    __shared__ unsigned long long skeys[1024];
    __shared__ unsigned long long wred[8];
    __shared__ int sel[KSEL];
    __shared__ float pooled[KSEL * PSTR];
    __shared__ float flat[COUT * LOUT];
    __shared__ float zz[HD];

    for (int i = tid; i < cnt; i += 256) {
        float v = h[(start + i) * HD + (HD - 1)];
        unsigned u = __float_as_uint(v);
        if (v == 0.0f) u = 0u;
        skeys[i] = ((unsigned long long)u << 32) |
                   (unsigned long long)(0xFFFFFFFFu - (unsigned)i);
    }
    for (int i = tid; i < KSEL * PSTR; i += 256) pooled[i] = 0.f;
    __syncthreads();

    const int m = (cnt < KSEL) ? cnt : KSEL;
    for (int r = 0; r < m; r++) {
        unsigned long long best = 0ULL;
        for (int i = tid; i < cnt; i += 256) {
            unsigned long long k = skeys[i];
            if (k > best) best = k;
        }
        #pragma unroll
        for (int off = 16; off > 0; off >>= 1) {
            unsigned long long o = __shfl_xor_sync(0xFFFFFFFFu, best, off);
            if (o > best) best = o;
        }
        if (lane == 0) wred[wid] = best;
        __syncthreads();
        if (tid == 0) {
            unsigned long long bk = 0ULL;
            #pragma unroll
            for (int qx = 0; qx < 8; qx++) if (wred[qx] > bk) bk = wred[qx];
            int i = (int)(0xFFFFFFFFu - (unsigned)(bk & 0xFFFFFFFFull));
            sel[r] = start + i;
            skeys[i] = 0ULL;
        }
        __syncthreads();
    }

    for (int idx = tid; idx < m * HD; idx += 256) {
        int r = idx >> 7, c = idx & 127;
        pooled[r * PSTR + c] = h[sel[r] * HD + c];
    }
    __syncthreads();

    for (int ot = tid; ot < COUT * LOUT; ot += 256) {
        int o = ot / LOUT, t = ot % LOUT;
        float s = __ldg(&cb[o]);
        const float* wo = cw + o * HD * KERW;
        for (int c = 0; c < HD; c++) {
            float w0 = __ldg(&wo[c * KERW + 0]);
            float w1 = __ldg(&wo[c * KERW + 1]);
            float w2 = __ldg(&wo[c * KERW + 2]);
            float w3 = __ldg(&wo[c * KERW + 3]);
            float w4 = __ldg(&wo[c * KERW + 4]);
            s += pooled[(t + 0) * PSTR + c] * w0;
            s += pooled[(t + 1) * PSTR + c] * w1;
            s += pooled[(t + 2) * PSTR + c] * w2;
            s += pooled[(t + 3) * PSTR + c] * w3;
            s += pooled[(t + 4) * PSTR + c] * w4;
        }
        flat[ot] = fmaxf(s, 0.f);
    }
    __syncthreads();

    if (tid < HD) {
        float s = __ldg(&l1b[tid]);
        #pragma unroll 8
        for (int i = 0; i < COUT * LOUT; i++)
            s += flat[i] * __ldg(&l1w[i * HD + tid]);
        zz[tid] = fmaxf(s, 0.f);
    }
    __syncthreads();

    if (tid < ODIM) {
        float s = __ldg(&l2b[tid]);
        #pragma unroll 8
        for (int i = 0; i < HD; i++)
            s += zz[i] * __ldg(&l2w[i * ODIM + tid]);
        out[b * ODIM + tid] = s;
    }
}

// ---------------- launch ----------------
static cudaStream_t g_s2 = nullptr;
static cudaEvent_t  g_e0 = nullptr, g_e1 = nullptr;

extern "C" void kernel_launch(void* const* d_in, const int* in_sizes, int n_in,
                              void* d_out, int out_size) {
    const float* x     = (const float*)d_in[0];
    const int*   ei    = (const int*)  d_in[1];
    const int*   batch = (const int*)  d_in[2];
    const float* W0 = (const float*)d_in[3];  const float* b0 = (const float*)d_in[4];
    const float* W1 = (const float*)d_in[5];  const float* b1 = (const float*)d_in[6];
    const float* W2 = (const float*)d_in[7];  const float* b2 = (const float*)d_in[8];
    const float* cw = (const float*)d_in[9];  const float* cb = (const float*)d_in[10];
    const float* l1w = (const float*)d_in[11]; const float* l1b = (const float*)d_in[12];
    const float* l2w = (const float*)d_in[13]; const float* l2b = (const float*)d_in[14];
    float* out = (float*)d_out;

    if (g_s2 == nullptr) {
        cudaStreamCreateWithFlags(&g_s2, cudaStreamNonBlocking);
        cudaEventCreateWithFlags(&g_e0, cudaEventDisableTiming);
        cudaEventCreateWithFlags(&g_e1, cudaEventDisableTiming);
    }
    const bool fork = (g_s2 != nullptr && g_e0 != nullptr && g_e1 != nullptr);
    cudaStream_t cs = fork ? g_s2 : (cudaStream_t)0;

    void *pA = nullptr, *pB = nullptr;
    cudaGetSymbolAddress(&pA, g_hA);
    cudaGetSymbolAddress(&pB, g_hB);
    float* hA = (float*)pA;
    float* hB = (float*)pB;

    if (fork) {
        cudaEventRecord(g_e0, 0);
        cudaStreamWaitEvent(cs, g_e0, 0);
    }
    k_init<<<(NN + 255) / 256, 256, 0, cs>>>();
    k_fill<<<(TE + 255) / 256, 256, 0, cs>>>(ei);
    k_dinv<<<(NN + 255) / 256, 256, 0, cs>>>();
    if (fork) cudaEventRecord(g_e1, cs);

    const int gemm_blocks = (NN + 127) / 128;   // 391
    const int agg_blocks  = (NN + 7) / 8;       // 6250

    // layer 1: GEMM overlaps CSR build; agg gathers dinv, writes dinv-scaled output
    k_gemm<<<gemm_blocks, 256>>>(x, W0);
    if (fork) cudaStreamWaitEvent(0, g_e1, 0);
    k_agg<true, true><<<agg_blocks, 256>>>(b0, hA);

    // layer 2: input rows pre-scaled -> no per-edge dinv; output scaled again
    k_gemm<<<gemm_blocks, 256>>>(hA, W1);
    k_agg<false, true><<<agg_blocks, 256>>>(b1, hB);

    // layer 3: input rows pre-scaled; output UNscaled (feeds head)
    k_gemm<<<gemm_blocks, 256>>>(hB, W2);
    k_agg<false, false><<<agg_blocks, 256>>>(b2, hA);

    k_head<<<BB, 256>>>(batch, hA, cw, cb, l1w, l1b, l2w, l2b, out);
}

// round 7
// speedup vs baseline: 1.1141x; 1.0831x over previous
#include <cuda_runtime.h>
#include <cstdint>

#define NN    50000
#define NE    600000
#define TE    (NE + NN)
#define HD    128
#define BB    128
#define KSEL  30
#define COUT  32
#define KERW  5
#define LOUT  26
#define ODIM  10
#define PSTR  129
#define DSLOT 64      // fixed per-node edge slots (Poisson(13) -> max deg << 64)

// ---------------- device scratch ----------------
static __device__ int   g_cur[NN];
static __device__ float g_dinv[NN];
static __device__ __align__(16) int g_srcv[NN * DSLOT];
static __device__ float g_hw[NN * HD];
static __device__ float g_hA[NN * HD];
static __device__ float g_hB[NN * HD];

// ---------------- f32x2 packed helpers ----------------
__device__ __forceinline__ unsigned long long pk2(float a, float b) {
    unsigned long long r;
    asm("mov.b64 %0, {%1, %2};" : "=l"(r) : "f"(a), "f"(b));
    return r;
}
__device__ __forceinline__ void fma2(unsigned long long& d, unsigned long long a, unsigned long long b) {
    asm("fma.rn.f32x2 %0, %1, %2, %0;" : "+l"(d) : "l"(a), "l"(b));
}

// ---------------- graph build (bucketed, no scan) ----------------
__global__ void k_init() {
    int i = blockIdx.x * 256 + threadIdx.x;
    if (i < NN) g_cur[i] = 0;
}

__global__ void k_fill(const int* __restrict__ ei) {
    int e = blockIdx.x * 256 + threadIdx.x;
    if (e >= TE) return;
    int src, dst;
    if (e < NE) { src = ei[e]; dst = ei[NE + e]; }
    else        { src = dst = e - NE; }          // self-loop
    int pos = atomicAdd(&g_cur[dst], 1);
    if (pos < DSLOT) g_srcv[dst * DSLOT + pos] = src;
}

__global__ void k_dinv() {
    int i = blockIdx.x * 256 + threadIdx.x;
    if (i < NN) g_dinv[i] = rsqrtf((float)g_cur[i]);
}

// ---------------- GEMM: g_hw = A(NNxHD) @ W(HDxHD), double-buffered smem --------
// 256 threads, block tile 128x128, thread tile 8x8, k-block 16, 2 smem buffers.
__global__ __launch_bounds__(256, 2) void k_gemm(const float* __restrict__ A,
                                                 const float* __restrict__ W) {
    __shared__ float Ash[2][16][132];   // [buf][k][m], padded
    __shared__ float Bsh[2][16][128];   // [buf][k][n]
    const int tid = threadIdx.x;
    const int m0 = blockIdx.x * 128;
    const int ty = tid >> 4;            // 0..15 -> rows ty*8..+8
    const int tx = tid & 15;            // 0..15 -> cols {tx*4, 64+tx*4}

    // per-thread load coordinates
    const int am = (tid * 2) >> 2, aq = (tid * 2) & 3;           // A: 2 float4 each
    const int bk = (tid * 2) >> 5, bn = ((tid * 2) & 31) * 4;    // B: 2 float4 each

    unsigned long long acc[8][4];
    #pragma unroll
    for (int i = 0; i < 8; i++)
        #pragma unroll
        for (int j = 0; j < 4; j++) acc[i][j] = 0ULL;

    // prologue: load k-block 0 into buffer 0
    float4 ra[2], rb[2];
    {
        int row0 = m0 + am, row1 = m0 + am;   // (two consecutive q, same m for idx,idx+1 when aq<3)
        #pragma unroll
        for (int s = 0; s < 2; s++) {
            int idx = tid * 2 + s;
            int m = idx >> 2, q = idx & 3;
            int row = m0 + m;
            ra[s] = (row < NN) ? *reinterpret_cast<const float4*>(&A[row * HD + q * 4])
                               : make_float4(0.f, 0.f, 0.f, 0.f);
            int k = (tid * 2 + s) >> 5, n4 = ((tid * 2 + s) & 31) * 4;
            rb[s] = *reinterpret_cast<const float4*>(&W[k * HD + n4]);
        }
        (void)row0; (void)row1;
    }

    #pragma unroll
    for (int kb = 0; kb < 8; kb++) {
        const int cur = kb & 1;
        // store prefetched regs into current buffer
        #pragma unroll
        for (int s = 0; s < 2; s++) {
            int idx = tid * 2 + s;
            int m = idx >> 2, q = idx & 3;
            Ash[cur][q * 4 + 0][m] = ra[s].x; Ash[cur][q * 4 + 1][m] = ra[s].y;
            Ash[cur][q * 4 + 2][m] = ra[s].z; Ash[cur][q * 4 + 3][m] = ra[s].w;
            int k = idx >> 5, n4 = (idx & 31) * 4;
            *reinterpret_cast<float4*>(&Bsh[cur][k][n4]) = rb[s];
        }
        __syncthreads();
        // prefetch next k-block into regs (overlaps FMA below)
        if (kb < 7) {
            int k0 = (kb + 1) * 16;
            #pragma unroll
            for (int s = 0; s < 2; s++) {
                int idx = tid * 2 + s;
                int m = idx >> 2, q = idx & 3;
                int row = m0 + m;
                ra[s] = (row < NN) ? *reinterpret_cast<const float4*>(&A[row * HD + k0 + q * 4])
                                   : make_float4(0.f, 0.f, 0.f, 0.f);
                int k = idx >> 5, n4 = (idx & 31) * 4;
                rb[s] = *reinterpret_cast<const float4*>(&W[(k0 + k) * HD + n4]);
            }
        }
        #pragma unroll
        for (int k = 0; k < 16; k++) {
            float4 a0 = *reinterpret_cast<const float4*>(&Ash[cur][k][ty * 8]);
            float4 a1 = *reinterpret_cast<const float4*>(&Ash[cur][k][ty * 8 + 4]);
            float av[8] = {a0.x, a0.y, a0.z, a0.w, a1.x, a1.y, a1.z, a1.w};
            ulonglong2 b0 = *reinterpret_cast<const ulonglong2*>(&Bsh[cur][k][tx * 4]);
            ulonglong2 b1 = *reinterpret_cast<const ulonglong2*>(&Bsh[cur][k][64 + tx * 4]);
            unsigned long long bv[4] = {b0.x, b0.y, b1.x, b1.y};
            #pragma unroll
            for (int i = 0; i < 8; i++) {
                unsigned long long ad = pk2(av[i], av[i]);
                #pragma unroll
                for (int j = 0; j < 4; j++) fma2(acc[i][j], ad, bv[j]);
            }
        }
        __syncthreads();
    }
    #pragma unroll
    for (int i = 0; i < 8; i++) {
        int row = m0 + ty * 8 + i;
        if (row < NN) {
            union { unsigned long long u[2]; float4 f; } p0, p1;
            p0.u[0] = acc[i][0]; p0.u[1] = acc[i][1];
            p1.u[0] = acc[i][2]; p1.u[1] = acc[i][3];
            *reinterpret_cast<float4*>(&g_hw[row * HD + tx * 4])      = p0.f;
            *reinterpret_cast<float4*>(&g_hw[row * HD + 64 + tx * 4]) = p1.f;
        }
    }
    (void)am; (void)aq; (void)bk; (void)bn;
}

// ---------------- aggregation: warp per node, 8 rows in flight ----------------
// GATHER_DINV: per-edge dinv scaling (layer 1 only).
// SCALE_OUT:   multiply relu output by dinv[w] (pre-scales rows for next layer).
template<bool GATHER_DINV, bool SCALE_OUT>
__global__ __launch_bounds__(256) void k_agg(const float* __restrict__ bias,
                                             float* __restrict__ hout) {
    int w = (blockIdx.x * 256 + threadIdx.x) >> 5;
    int lane = threadIdx.x & 31;
    if (w >= NN) return;
    int deg = g_cur[w]; if (deg > DSLOT) deg = DSLOT;
    const int* lst = &g_srcv[w * DSLOT];
    const float4* hw4 = reinterpret_cast<const float4*>(g_hw);
    float4 acc = make_float4(0.f, 0.f, 0.f, 0.f);

    int e = 0;
    for (; e + 8 <= deg; e += 8) {
        int s[8];
        #pragma unroll
        for (int u = 0; u < 8; u++) s[u] = __ldg(&lst[e + u]);   // warp-uniform, L1 broadcast
        float c[8];
        #pragma unroll
        for (int u = 0; u < 8; u++) c[u] = GATHER_DINV ? __ldg(&g_dinv[s[u]]) : 1.f;
        float4 v[8];
        #pragma unroll
        for (int u = 0; u < 8; u++) v[u] = __ldg(&hw4[s[u] * 32 + lane]);  // 8 in flight
        #pragma unroll
        for (int u = 0; u < 8; u++) {
            if (GATHER_DINV) {
                acc.x += c[u] * v[u].x; acc.y += c[u] * v[u].y;
                acc.z += c[u] * v[u].z; acc.w += c[u] * v[u].w;
            } else {
                acc.x += v[u].x; acc.y += v[u].y;
                acc.z += v[u].z; acc.w += v[u].w;
            }
        }
    }
    if (e + 4 <= deg) {
        int s[4];
        #pragma unroll
        for (int u = 0; u < 4; u++) s[u] = __ldg(&lst[e + u]);
        float c[4];
        #pragma unroll
        for (int u = 0; u < 4; u++) c[u] = GATHER_DINV ? __ldg(&g_dinv[s[u]]) : 1.f;
        float4 v[4];
        #pragma unroll
        for (int u = 0; u < 4; u++) v[u] = __ldg(&hw4[s[u] * 32 + lane]);
        #pragma unroll
        for (int u = 0; u < 4; u++) {
            if (GATHER_DINV) {
                acc.x += c[u] * v[u].x; acc.y += c[u] * v[u].y;
                acc.z += c[u] * v[u].z; acc.w += c[u] * v[u].w;
            } else {
                acc.x += v[u].x; acc.y += v[u].y;
                acc.z += v[u].z; acc.w += v[u].w;
            }
        }
        e += 4;
    }
    for (; e < deg; e++) {
        int s = __ldg(&lst[e]);
        float c = GATHER_DINV ? __ldg(&g_dinv[s]) : 1.f;
        float4 v = __ldg(&hw4[s * 32 + lane]);
        if (GATHER_DINV) {
            acc.x += c * v.x; acc.y += c * v.y; acc.z += c * v.z; acc.w += c * v.w;
        } else {
            acc.x += v.x; acc.y += v.y; acc.z += v.z; acc.w += v.w;
        }
    }

    float dn = g_dinv[w];
    float4 bb = reinterpret_cast<const float4*>(bias)[lane];
    float4 r;
    r.x = fmaxf(acc.x * dn + bb.x, 0.f);
    r.y = fmaxf(acc.y * dn + bb.y, 0.f);
    r.z = fmaxf(acc.z * dn + bb.z, 0.f);
    r.w = fmaxf(acc.w * dn + bb.w, 0.f);
    if (SCALE_OUT) { r.x *= dn; r.y *= dn; r.z *= dn; r.w *= dn; }
    reinterpret_cast<float4*>(hout)[w * 32 + lane] = r;
}

// ---------------- sort-pool + conv1d + MLP ----------------
__device__ __forceinline__ int lbound(const int* __restrict__ a, int n, int key) {
    int lo = 0, hi = n;
    while (lo < hi) { int mid = (lo + hi) >> 1; if (a[mid] < key) lo = mid + 1; else hi = mid; }
    return lo;
}

__global__ __launch_bounds__(256) void k_head(const int* __restrict__ batch,
                                              const float* __restrict__ h,
                                              const float* __restrict__ cw,
                                              const float* __restrict__ cb,
                                              const float* __restrict__ l1w,
                                              const float* __restrict__ l1b,
                                              const float* __restrict__ l2w,
                                              const float* __restrict__ l2b,
                                              float* __restrict__ out) {
    const int b = blockIdx.x, tid = threadIdx.x;
    const int lane = tid & 31, wid = tid >> 5;
    const int start = lbound(batch, NN, b);
    const int end   = lbound(batch, NN, b + 1);
    int cnt = end - start;
    if (cnt > 1024) cnt = 1024;

    __shared__ unsigned long long skeys[1024];
    __shared__ unsigned long long wred[8];
    __shared__ int sel[KSEL];
    __shared__ float pooled[KSEL * PSTR];
    __shared__ float flat[COUT * LOUT];
    __shared__ float zz[HD];

    for (int i = tid; i < cnt; i += 256) {
        float v = h[(start + i) * HD + (HD - 1)];
        unsigned u = __float_as_uint(v);
        if (v == 0.0f) u = 0u;
        skeys[i] = ((unsigned long long)u << 32) |
                   (unsigned long long)(0xFFFFFFFFu - (unsigned)i);
    }
    for (int i = tid; i < KSEL * PSTR; i += 256) pooled[i] = 0.f;
    __syncthreads();

    const int m = (cnt < KSEL) ? cnt : KSEL;
    for (int r = 0; r < m; r++) {
        unsigned long long best = 0ULL;
        for (int i = tid; i < cnt; i += 256) {
            unsigned long long k = skeys[i];
            if (k > best) best = k;
        }
        #pragma unroll
        for (int off = 16; off > 0; off >>= 1) {
            unsigned long long o = __shfl_xor_sync(0xFFFFFFFFu, best, off);
            if (o > best) best = o;
        }
        if (lane == 0) wred[wid] = best;
        __syncthreads();
        if (tid == 0) {
            unsigned long long bk = 0ULL;
            #pragma unroll
            for (int qx = 0; qx < 8; qx++) if (wred[qx] > bk) bk = wred[qx];
            int i = (int)(0xFFFFFFFFu - (unsigned)(bk & 0xFFFFFFFFull));
            sel[r] = start + i;
            skeys[i] = 0ULL;
        }
        __syncthreads();
    }

    for (int idx = tid; idx < m * HD; idx += 256) {
        int r = idx >> 7, c = idx & 127;
        pooled[r * PSTR + c] = h[sel[r] * HD + c];
    }
    __syncthreads();

    for (int ot = tid; ot < COUT * LOUT; ot += 256) {
        int o = ot / LOUT, t = ot % LOUT;
        float s = __ldg(&cb[o]);
        const float* wo = cw + o * HD * KERW;
        for (int c = 0; c < HD; c++) {
            float w0 = __ldg(&wo[c * KERW + 0]);
            float w1 = __ldg(&wo[c * KERW + 1]);
            float w2 = __ldg(&wo[c * KERW + 2]);
            float w3 = __ldg(&wo[c * KERW + 3]);
            float w4 = __ldg(&wo[c * KERW + 4]);
            s += pooled[(t + 0) * PSTR + c] * w0;
            s += pooled[(t + 1) * PSTR + c] * w1;
            s += pooled[(t + 2) * PSTR + c] * w2;
            s += pooled[(t + 3) * PSTR + c] * w3;
            s += pooled[(t + 4) * PSTR + c] * w4;
        }
        flat[ot] = fmaxf(s, 0.f);
    }
    __syncthreads();

    if (tid < HD) {
        float s = __ldg(&l1b[tid]);
        #pragma unroll 8
        for (int i = 0; i < COUT * LOUT; i++)
            s += flat[i] * __ldg(&l1w[i * HD + tid]);
        zz[tid] = fmaxf(s, 0.f);
    }
    __syncthreads();

    if (tid < ODIM) {
        float s = __ldg(&l2b[tid]);
        #pragma unroll 8
        for (int i = 0; i < HD; i++)
            s += zz[i] * __ldg(&l2w[i * ODIM + tid]);
        out[b * ODIM + tid] = s;
    }
}

// ---------------- launch ----------------
static cudaStream_t g_s2 = nullptr;
static cudaEvent_t  g_e0 = nullptr, g_e1 = nullptr;

extern "C" void kernel_launch(void* const* d_in, const int* in_sizes, int n_in,
                              void* d_out, int out_size) {
    const float* x     = (const float*)d_in[0];
    const int*   ei    = (const int*)  d_in[1];
    const int*   batch = (const int*)  d_in[2];
    const float* W0 = (const float*)d_in[3];  const float* b0 = (const float*)d_in[4];
    const float* W1 = (const float*)d_in[5];  const float* b1 = (const float*)d_in[6];
    const float* W2 = (const float*)d_in[7];  const float* b2 = (const float*)d_in[8];
    const float* cw = (const float*)d_in[9];  const float* cb = (const float*)d_in[10];
    const float* l1w = (const float*)d_in[11]; const float* l1b = (const float*)d_in[12];
    const float* l2w = (const float*)d_in[13]; const float* l2b = (const float*)d_in[14];
    float* out = (float*)d_out;

    if (g_s2 == nullptr) {
        cudaStreamCreateWithFlags(&g_s2, cudaStreamNonBlocking);
        cudaEventCreateWithFlags(&g_e0, cudaEventDisableTiming);
        cudaEventCreateWithFlags(&g_e1, cudaEventDisableTiming);
    }
    const bool fork = (g_s2 != nullptr && g_e0 != nullptr && g_e1 != nullptr);
    cudaStream_t cs = fork ? g_s2 : (cudaStream_t)0;

    void *pA = nullptr, *pB = nullptr;
    cudaGetSymbolAddress(&pA, g_hA);
    cudaGetSymbolAddress(&pB, g_hB);
    float* hA = (float*)pA;
    float* hB = (float*)pB;

    if (fork) {
        cudaEventRecord(g_e0, 0);
        cudaStreamWaitEvent(cs, g_e0, 0);
    }
    k_init<<<(NN + 255) / 256, 256, 0, cs>>>();
    k_fill<<<(TE + 255) / 256, 256, 0, cs>>>(ei);
    k_dinv<<<(NN + 255) / 256, 256, 0, cs>>>();
    if (fork) cudaEventRecord(g_e1, cs);

    const int gemm_blocks = (NN + 127) / 128;   // 391
    const int agg_blocks  = (NN + 7) / 8;       // 6250

    // layer 1: GEMM overlaps CSR build; agg gathers per-edge dinv, writes pre-scaled rows
    k_gemm<<<gemm_blocks, 256>>>(x, W0);
    if (fork) cudaStreamWaitEvent(0, g_e1, 0);
    k_agg<true, true><<<agg_blocks, 256>>>(b0, hA);

    // layer 2: rows pre-scaled -> pure row-sum gather; output pre-scaled again
    k_gemm<<<gemm_blocks, 256>>>(hA, W1);
    k_agg<false, true><<<agg_blocks, 256>>>(b1, hB);

    // layer 3: rows pre-scaled; output UNscaled (feeds head)
    k_gemm<<<gemm_blocks, 256>>>(hB, W2);
    k_agg<false, false><<<agg_blocks, 256>>>(b2, hA);

    k_head<<<BB, 256>>>(batch, hA, cw, cb, l1w, l1b, l2w, l2b, out);
}